// round 15
// baseline (speedup 1.0000x reference)
#include <cuda_runtime.h>
#include <math.h>
#include <mma.h>

using namespace nvcuda;

#define BB 32
#define LL 128
#define DD 300
#define HH 1024
#define G4 4096
#define G6 6144
#define K3 3072
#define NMAX 4096
#define LVMAX 2048

// ---------------- static device scratch (no runtime allocation) ----------------
__device__ __align__(256) float g_Xg[BB * LL * G4];   // 67 MB: x@W_ih^T + b_ih + b_hh
__device__ __align__(256) float g_hs[BB * LL * HH];   // leaf h
__device__ __align__(256) float g_cs[BB * LL * HH];   // leaf c
__device__ __align__(256) float g_nh[NMAX * HH];      // internal node h
__device__ __align__(256) float g_nc[NMAX * HH];      // internal node c
__device__ __align__(256) float g_gp[LVMAX * G6];     // 50 MB: compose gate plane
__device__ int g_nl[NMAX];
__device__ int g_nr[NMAX];
__device__ int g_nx[NMAX];
__device__ int g_lvl_cnt[LL];
__device__ int g_lvl_list[LL * LVMAX];
__device__ int g_root[BB];

__device__ __forceinline__ float sigf(float x) { return 1.0f / (1.0f + expf(-x)); }

// =====================================================================
// K1: Xg[m][n] = X[m][:300] . W_ih[n][:300] + b_ih[n] + b_hh[n]
// M = 4096 (b*L+t), N = 4096, K = 300. 64x64 tile, 4x4 per thread.
// =====================================================================
__global__ __launch_bounds__(256) void xg_gemm(const float* __restrict__ X,
                                               const float* __restrict__ Wih,
                                               const float* __restrict__ bih,
                                               const float* __restrict__ bhh) {
    __shared__ float As[64][17];
    __shared__ float Bs[64][17];
    const int tid = threadIdx.x;
    const int m0 = blockIdx.y << 6;
    const int n0 = blockIdx.x << 6;
    const int m4 = (tid & 15) << 2;
    const int n4 = (tid >> 4) << 2;
    const int lr = tid >> 2;
    const int lk = (tid & 3) << 2;
    float acc[4][4];
#pragma unroll
    for (int i = 0; i < 4; i++)
#pragma unroll
        for (int j = 0; j < 4; j++) acc[i][j] = 0.0f;

    for (int k0 = 0; k0 < DD; k0 += 16) {
#pragma unroll
        for (int q = 0; q < 4; q++) {
            int k = k0 + lk + q;
            As[lr][lk + q] = (k < DD) ? X[(size_t)(m0 + lr) * DD + k] : 0.0f;
            Bs[lr][lk + q] = (k < DD) ? Wih[(size_t)(n0 + lr) * DD + k] : 0.0f;
        }
        __syncthreads();
#pragma unroll
        for (int kk = 0; kk < 16; kk++) {
            float a[4], bv[4];
#pragma unroll
            for (int i = 0; i < 4; i++) a[i] = As[m4 + i][kk];
#pragma unroll
            for (int j = 0; j < 4; j++) bv[j] = Bs[n4 + j][kk];
#pragma unroll
            for (int i = 0; i < 4; i++)
#pragma unroll
                for (int j = 0; j < 4; j++) acc[i][j] += a[i] * bv[j];
        }
        __syncthreads();
    }
#pragma unroll
    for (int i = 0; i < 4; i++) {
        int m = m0 + m4 + i;
#pragma unroll
        for (int j = 0; j < 4; j++) {
            int n = n0 + n4 + j;
            g_Xg[(size_t)m * G4 + n] = acc[i][j] + bih[n] + bhh[n];
        }
    }
}

// =====================================================================
// K2: FUSED LSTM step t, DOUBLE-BUFFERED (unchanged, measured 24.5us).
// =====================================================================
__global__ __launch_bounds__(256) void lstm_step(int t, const float* __restrict__ Whh) {
    __shared__ float Hs[2][64][34];   // [buf][k][batch]
    __shared__ float Ws[2][64][34];   // [buf][k][row]
    __shared__ float Gs[32][33];      // [batch][row] gate preacts
    const int tid = threadIdx.x;
    const int j0 = blockIdx.x << 3;
    const int nb = (tid & 15) << 1;   // row pair
    const int mb = (tid >> 4) << 1;   // batch pair
    float acc[2][2] = {{0.f, 0.f}, {0.f, 0.f}};

    if (t > 0) {
        const size_t hbase = (size_t)(t - 1) * HH;
#pragma unroll
        for (int it = 0; it < 8; it++) {
            int lin = tid + (it << 8);
            int kk = lin & 63, b = lin >> 6;
            Hs[0][kk][b] = g_hs[(size_t)b * LL * HH + hbase + kk];
        }
#pragma unroll
        for (int it = 0; it < 8; it++) {
            int lin = tid + (it << 8);
            int kk = lin & 63, n = lin >> 6;
            int R = ((n >> 3) << 10) + j0 + (n & 7);
            Ws[0][kk][n] = Whh[(size_t)R * HH + kk];
        }
        __syncthreads();

        for (int c = 0; c < 16; c++) {
            const int cur = c & 1;
            const int nxt = cur ^ 1;
            float hreg[8], wreg[8];
            if (c < 15) {
                int k0 = (c + 1) << 6;
#pragma unroll
                for (int it = 0; it < 8; it++) {
                    int lin = tid + (it << 8);
                    int kk = lin & 63, b = lin >> 6;
                    hreg[it] = g_hs[(size_t)b * LL * HH + hbase + k0 + kk];
                }
#pragma unroll
                for (int it = 0; it < 8; it++) {
                    int lin = tid + (it << 8);
                    int kk = lin & 63, n = lin >> 6;
                    int R = ((n >> 3) << 10) + j0 + (n & 7);
                    wreg[it] = Whh[(size_t)R * HH + k0 + kk];
                }
            }
#pragma unroll 16
            for (int kk = 0; kk < 64; kk++) {
                float2 av = *(const float2*)&Hs[cur][kk][mb];
                float2 bv = *(const float2*)&Ws[cur][kk][nb];
                acc[0][0] += av.x * bv.x; acc[0][1] += av.x * bv.y;
                acc[1][0] += av.y * bv.x; acc[1][1] += av.y * bv.y;
            }
            if (c < 15) {
#pragma unroll
                for (int it = 0; it < 8; it++) {
                    int lin = tid + (it << 8);
                    int kk = lin & 63, b = lin >> 6;
                    Hs[nxt][kk][b] = hreg[it];
                }
#pragma unroll
                for (int it = 0; it < 8; it++) {
                    int lin = tid + (it << 8);
                    int kk = lin & 63, n = lin >> 6;
                    Ws[nxt][kk][n] = wreg[it];
                }
            }
            __syncthreads();
        }
    }

#pragma unroll
    for (int i = 0; i < 2; i++) {
        int b = mb + i;
#pragma unroll
        for (int j = 0; j < 2; j++) {
            int n = nb + j;
            int col = ((n >> 3) << 10) + j0 + (n & 7);
            Gs[b][n] = acc[i][j] + g_Xg[((size_t)b * LL + t) * G4 + col];
        }
    }
    __syncthreads();

    {
        int b = tid >> 3;
        int jj = tid & 7;
        float gi = Gs[b][jj];
        float gf = Gs[b][8 + jj];
        float gg = Gs[b][16 + jj];
        float go = Gs[b][24 + jj];
        float cp = (t > 0) ? g_cs[((size_t)b * LL + (t - 1)) * HH + j0 + jj] : 0.0f;
        float c = sigf(gf) * cp + sigf(gi) * tanhf(gg);
        float h = sigf(go) * tanhf(c);
        g_hs[((size_t)b * LL + t) * HH + j0 + jj] = h;
        g_cs[((size_t)b * LL + t) * HH + j0 + jj] = c;
    }
}

// =====================================================================
// K4: device-side greedy tree build (1 thread per batch)
// =====================================================================
__global__ void build_tree(const int* __restrict__ words, const int* __restrict__ length) {
    int tid = threadIdx.x;
    if (tid < LL) g_lvl_cnt[tid] = 0;
    __syncthreads();
    if (tid >= BB) return;
    int b = tid;
    const int* w = words + b * LL;
    int nlen = length[b];
    int df[LL];
    for (int i = 0; i < nlen; i++) df[i] = w[i] % 1000;

    int st_start[132], st_end[132], st_pos[132], st_stage[132], st_left[132], st_llvl[132];
    int sp = 0;
    st_start[0] = 0; st_end[0] = nlen; st_stage[0] = 0;
    int retE = -1, retL = 0;
    int localCount = 0;

    while (sp >= 0) {
        int stage = st_stage[sp];
        if (stage == 0) {
            int s = st_start[sp], e = st_end[sp], n = e - s;
            if (n == 0) { retE = -1; retL = 0; sp--; }
            else if (n == 1) { retE = 100000 + b * LL + s; retL = 0; sp--; }
            else {
                int best = s;
                for (int i = s + 1; i < e; i++)
                    if (df[i] < df[best]) best = i;
                st_pos[sp] = best;
                st_stage[sp] = 1;
                sp++;
                st_start[sp] = s; st_end[sp] = best; st_stage[sp] = 0;
            }
        } else if (stage == 1) {
            st_left[sp] = retE; st_llvl[sp] = retL; st_stage[sp] = 2;
            int p = st_pos[sp];
            int e = st_end[sp];
            sp++;
            st_start[sp] = p + 1; st_end[sp] = e; st_stage[sp] = 0;
        } else {
            int id = b * 127 + (localCount++);
            g_nl[id] = st_left[sp];
            g_nr[id] = retE;
            g_nx[id] = b * LL + st_pos[sp];
            int lvl = 1 + (st_llvl[sp] > retL ? st_llvl[sp] : retL);
            int pos = atomicAdd(&g_lvl_cnt[lvl], 1);
            g_lvl_list[lvl * LVMAX + pos] = id;
            retE = id; retL = lvl;
            sp--;
        }
    }
    g_root[b] = retE;
}

// =====================================================================
// K6: compose GEMM for level lvl — wmma tf32, FULL-K, double-buffered.
//   gp[m][n] = A[m][0:3072] . W_comp[n][0:3072]
// A row m = cat[h_left | h_x | h_right] gathered from children (null -> 0).
// Tile 64x128: 8 warps as 2(m) x 4(n), warp = 32x32 = 2x2 wmma m16n16k8.
// K processed in 192 chunks of 16; next chunk register-prefetched while
// current chunk computes; ping-pong smem; ONE barrier per chunk.
// Pad 24 floats (96B rows): 32B-aligned frag bases at kq in {0,8}.
// Padded rows (m >= cnt) write zeros to gp rows < LVMAX; harmless.
// =====================================================================
__global__ __launch_bounds__(256) void compose_gemm(int lvl, const float* __restrict__ Wc) {
    int cnt = g_lvl_cnt[lvl];
    if (cnt == 0) return;
    __shared__ __align__(32) float As[2][64][24];    // [buf][m][k] tf32 bits
    __shared__ __align__(32) float Bs[2][128][24];   // [buf][n][k] tf32 bits
    __shared__ const float* rph[64][3];
    const int tid = threadIdx.x;
    const int wid = tid >> 5;
    const int n0 = blockIdx.x << 7;
    const int wm = (wid & 1) << 5;     // warp m offset: 0 / 32
    const int wn = (wid >> 1) << 5;    // warp n offset: 0 / 32 / 64 / 96
    // staging coords (k-chunk = 16)
    const int sA_r = tid >> 4;         // A row for it-loop: r = tid>>4 + it*16? (see below)
    const int sk = tid & 15;           // k within chunk

    for (int mt = blockIdx.y; mt * 64 < cnt; mt += gridDim.y) {
        int m0 = mt << 6;
        if (tid < 192) {
            int r = tid / 3, s = tid % 3;
            int m = m0 + r;
            const float* p = nullptr;
            if (m < cnt) {
                int id = g_lvl_list[lvl * LVMAX + m];
                int enc = (s == 0) ? g_nl[id] : (s == 1 ? (100000 + g_nx[id]) : g_nr[id]);
                if (enc >= 100000) p = g_hs + (size_t)(enc - 100000) * HH;
                else if (enc >= 0) p = g_nh + (size_t)enc * HH;
            }
            rph[r][s] = p;
        }
        __syncthreads();

        wmma::fragment<wmma::accumulator, 16, 16, 8, float> cf[2][2];
#pragma unroll
        for (int i = 0; i < 2; i++)
#pragma unroll
            for (int j = 0; j < 2; j++) wmma::fill_fragment(cf[i][j], 0.0f);

        // prologue: chunk 0 -> buf 0
        {
#pragma unroll
            for (int it = 0; it < 4; it++) {
                int r = sA_r + (it << 4);             // 0..63
                const float* p = rph[r][0];           // k0=0 -> seg 0
                As[0][r][sk] = wmma::__float_to_tf32(p ? p[sk] : 0.0f);
            }
#pragma unroll
            for (int it = 0; it < 8; it++) {
                int n = sA_r + (it << 4);             // 0..127
                Bs[0][n][sk] = wmma::__float_to_tf32(Wc[(size_t)(n0 + n) * K3 + sk]);
            }
        }
        __syncthreads();

        for (int c = 0; c < 192; c++) {
            const int cur = c & 1;
            const int nxt = cur ^ 1;
            float aReg[4], bReg[8];
            if (c < 191) {
                int k0 = (c + 1) << 4;
                int seg = k0 >> 10;
                int koff = (k0 & 1023) + sk;
#pragma unroll
                for (int it = 0; it < 4; it++) {
                    int r = sA_r + (it << 4);
                    const float* p = rph[r][seg];
                    aReg[it] = p ? p[koff] : 0.0f;
                }
#pragma unroll
                for (int it = 0; it < 8; it++) {
                    int n = sA_r + (it << 4);
                    bReg[it] = Wc[(size_t)(n0 + n) * K3 + k0 + sk];
                }
            }
#pragma unroll
            for (int kq = 0; kq < 16; kq += 8) {
                wmma::fragment<wmma::matrix_a, 16, 16, 8, wmma::precision::tf32, wmma::row_major> af[2];
                wmma::fragment<wmma::matrix_b, 16, 16, 8, wmma::precision::tf32, wmma::col_major> bf[2];
                wmma::load_matrix_sync(af[0], &As[cur][wm][kq], 24);
                wmma::load_matrix_sync(af[1], &As[cur][wm + 16][kq], 24);
                wmma::load_matrix_sync(bf[0], &Bs[cur][wn][kq], 24);
                wmma::load_matrix_sync(bf[1], &Bs[cur][wn + 16][kq], 24);
#pragma unroll
                for (int i = 0; i < 2; i++)
#pragma unroll
                    for (int j = 0; j < 2; j++)
                        wmma::mma_sync(cf[i][j], af[i], bf[j], cf[i][j]);
            }
            if (c < 191) {
#pragma unroll
                for (int it = 0; it < 4; it++)
                    As[nxt][sA_r + (it << 4)][sk] = wmma::__float_to_tf32(aReg[it]);
#pragma unroll
                for (int it = 0; it < 8; it++)
                    Bs[nxt][sA_r + (it << 4)][sk] = wmma::__float_to_tf32(bReg[it]);
            }
            __syncthreads();
        }

        // store 2x2 16x16 accum tiles to the gate plane (row-major, ld=G6)
#pragma unroll
        for (int i = 0; i < 2; i++)
#pragma unroll
            for (int j = 0; j < 2; j++)
                wmma::store_matrix_sync(
                    &g_gp[(size_t)(m0 + wm + i * 16) * G6 + n0 + wn + j * 16],
                    cf[i][j], G6, wmma::mem_row_major);
        __syncthreads();
    }
}

// =====================================================================
// K7: compose pointwise for level lvl (NaryLSTM cell); single gate plane
// =====================================================================
__device__ __forceinline__ float fetch_c(int enc, int j) {
    if (enc < 0) return 0.0f;
    if (enc >= 100000) return g_cs[(size_t)(enc - 100000) * HH + j];
    return g_nc[(size_t)enc * HH + j];
}

__global__ __launch_bounds__(256) void compose_point(int lvl, const float* __restrict__ bc) {
    int cnt = g_lvl_cnt[lvl];
    int total = cnt * HH;
    int stride = gridDim.x * blockDim.x;
    for (int idx = blockIdx.x * blockDim.x + threadIdx.x; idx < total; idx += stride) {
        int m = idx >> 10;
        int j = idx & 1023;
        int id = g_lvl_list[lvl * LVMAX + m];
        float a[6];
#pragma unroll
        for (int s = 0; s < 6; s++)
            a[s] = g_gp[(size_t)m * G6 + (s << 10) + j] + bc[(s << 10) + j];
        int le = g_nl[id], re = g_nr[id], xs = g_nx[id];
        float cl = fetch_c(le, j);
        float cr = fetch_c(re, j);
        float cx = g_cs[(size_t)xs * HH + j];
        float c = sigf(a[0]) * tanhf(a[4]) + sigf(a[1]) * cl + sigf(a[2]) * cx + sigf(a[3]) * cr;
        float h = sigf(a[5]) * tanhf(c);
        g_nh[(size_t)id * HH + j] = h;
        g_nc[(size_t)id * HH + j] = c;
    }
}

// =====================================================================
// K8: gather roots -> output  [h (B,H) ; c (B,H)]
// =====================================================================
__global__ __launch_bounds__(256) void write_out(float* __restrict__ out) {
    int stride = gridDim.x * blockDim.x;
    for (int idx = blockIdx.x * blockDim.x + threadIdx.x; idx < BB * HH; idx += stride) {
        int b = idx >> 10;
        int j = idx & 1023;
        int r = g_root[b];
        out[idx] = g_nh[(size_t)r * HH + j];
        out[BB * HH + idx] = g_nc[(size_t)r * HH + j];
    }
}

// =====================================================================
extern "C" void kernel_launch(void* const* d_in, const int* in_sizes, int n_in,
                              void* d_out, int out_size) {
    const float* X    = (const float*)d_in[0];  // (32,128,300)
    const float* Wih  = (const float*)d_in[1];  // (4096,300)
    const float* Whh  = (const float*)d_in[2];  // (4096,1024)
    const float* bih  = (const float*)d_in[3];  // (4096)
    const float* bhh  = (const float*)d_in[4];  // (4096)
    const float* Wc   = (const float*)d_in[5];  // (6144,3072)
    const float* bc   = (const float*)d_in[6];  // (6144)
    const int* words  = (const int*)d_in[7];    // (32,128)
    const int* length = (const int*)d_in[8];    // (32)
    float* out = (float*)d_out;

    // Phase 0: input-projection GEMM + tree structure (independent)
    xg_gemm<<<dim3(64, 64), 256>>>(X, Wih, bih, bhh);
    build_tree<<<1, 128>>>(words, length);

    // Phase 1: leaf LSTM, 128 sequential fused steps
    for (int t = 0; t < LL; t++)
        lstm_step<<<128, 256>>>(t, Whh);

    // Phase 2: compose levels bottom-up (worst-case depth 127; empty levels no-op)
    for (int lvl = 1; lvl < LL; lvl++) {
        compose_gemm<<<dim3(48, 16), 256>>>(lvl, Wc);
        compose_point<<<64, 256>>>(lvl, bc);
    }

    // Phase 3: output
    write_out<<<32, 256>>>(out);
}

// round 17
// speedup vs baseline: 1.1499x; 1.1499x over previous
#include <cuda_runtime.h>
#include <math.h>
#include <mma.h>

using namespace nvcuda;

#define BB 32
#define LL 128
#define DD 300
#define HH 1024
#define G4 4096
#define G6 6144
#define K3 3072
#define NMAX 4096
#define LVMAX 2048
#define KSPLIT 4
#define KSLICE (K3 / KSPLIT)   // 768
#define NCHUNK (KSLICE / 16)   // 48

// ---------------- static device scratch (no runtime allocation) ----------------
__device__ __align__(256) float g_Xg[BB * LL * G4];          // 67 MB
__device__ __align__(256) float g_hs[BB * LL * HH];
__device__ __align__(256) float g_cs[BB * LL * HH];
__device__ __align__(256) float g_nh[NMAX * HH];
__device__ __align__(256) float g_nc[NMAX * HH];
__device__ __align__(256) float g_gp[KSPLIT * LVMAX * G6];   // 201 MB partials
__device__ int g_nl[NMAX];
__device__ int g_nr[NMAX];
__device__ int g_nx[NMAX];
__device__ int g_lvl_cnt[LL];
__device__ int g_lvl_list[LL * LVMAX];
__device__ int g_root[BB];

__device__ __forceinline__ float sigf(float x) { return 1.0f / (1.0f + expf(-x)); }

// =====================================================================
// K1: Xg[m][n] = X[m][:300] . W_ih[n][:300] + b_ih[n] + b_hh[n]
// =====================================================================
__global__ __launch_bounds__(256) void xg_gemm(const float* __restrict__ X,
                                               const float* __restrict__ Wih,
                                               const float* __restrict__ bih,
                                               const float* __restrict__ bhh) {
    __shared__ float As[64][17];
    __shared__ float Bs[64][17];
    const int tid = threadIdx.x;
    const int m0 = blockIdx.y << 6;
    const int n0 = blockIdx.x << 6;
    const int m4 = (tid & 15) << 2;
    const int n4 = (tid >> 4) << 2;
    const int lr = tid >> 2;
    const int lk = (tid & 3) << 2;
    float acc[4][4];
#pragma unroll
    for (int i = 0; i < 4; i++)
#pragma unroll
        for (int j = 0; j < 4; j++) acc[i][j] = 0.0f;

    for (int k0 = 0; k0 < DD; k0 += 16) {
#pragma unroll
        for (int q = 0; q < 4; q++) {
            int k = k0 + lk + q;
            As[lr][lk + q] = (k < DD) ? X[(size_t)(m0 + lr) * DD + k] : 0.0f;
            Bs[lr][lk + q] = (k < DD) ? Wih[(size_t)(n0 + lr) * DD + k] : 0.0f;
        }
        __syncthreads();
#pragma unroll
        for (int kk = 0; kk < 16; kk++) {
            float a[4], bv[4];
#pragma unroll
            for (int i = 0; i < 4; i++) a[i] = As[m4 + i][kk];
#pragma unroll
            for (int j = 0; j < 4; j++) bv[j] = Bs[n4 + j][kk];
#pragma unroll
            for (int i = 0; i < 4; i++)
#pragma unroll
                for (int j = 0; j < 4; j++) acc[i][j] += a[i] * bv[j];
        }
        __syncthreads();
    }
#pragma unroll
    for (int i = 0; i < 4; i++) {
        int m = m0 + m4 + i;
#pragma unroll
        for (int j = 0; j < 4; j++) {
            int n = n0 + n4 + j;
            g_Xg[(size_t)m * G4 + n] = acc[i][j] + bih[n] + bhh[n];
        }
    }
}

// =====================================================================
// K2: FUSED LSTM step t, DOUBLE-BUFFERED (measured 24.5us/step).
// =====================================================================
__global__ __launch_bounds__(256) void lstm_step(int t, const float* __restrict__ Whh) {
    __shared__ float Hs[2][64][34];
    __shared__ float Ws[2][64][34];
    __shared__ float Gs[32][33];
    const int tid = threadIdx.x;
    const int j0 = blockIdx.x << 3;
    const int nb = (tid & 15) << 1;
    const int mb = (tid >> 4) << 1;
    float acc[2][2] = {{0.f, 0.f}, {0.f, 0.f}};

    if (t > 0) {
        const size_t hbase = (size_t)(t - 1) * HH;
#pragma unroll
        for (int it = 0; it < 8; it++) {
            int lin = tid + (it << 8);
            int kk = lin & 63, b = lin >> 6;
            Hs[0][kk][b] = g_hs[(size_t)b * LL * HH + hbase + kk];
        }
#pragma unroll
        for (int it = 0; it < 8; it++) {
            int lin = tid + (it << 8);
            int kk = lin & 63, n = lin >> 6;
            int R = ((n >> 3) << 10) + j0 + (n & 7);
            Ws[0][kk][n] = Whh[(size_t)R * HH + kk];
        }
        __syncthreads();

        for (int c = 0; c < 16; c++) {
            const int cur = c & 1;
            const int nxt = cur ^ 1;
            float hreg[8], wreg[8];
            if (c < 15) {
                int k0 = (c + 1) << 6;
#pragma unroll
                for (int it = 0; it < 8; it++) {
                    int lin = tid + (it << 8);
                    int kk = lin & 63, b = lin >> 6;
                    hreg[it] = g_hs[(size_t)b * LL * HH + hbase + k0 + kk];
                }
#pragma unroll
                for (int it = 0; it < 8; it++) {
                    int lin = tid + (it << 8);
                    int kk = lin & 63, n = lin >> 6;
                    int R = ((n >> 3) << 10) + j0 + (n & 7);
                    wreg[it] = Whh[(size_t)R * HH + k0 + kk];
                }
            }
#pragma unroll 16
            for (int kk = 0; kk < 64; kk++) {
                float2 av = *(const float2*)&Hs[cur][kk][mb];
                float2 bv = *(const float2*)&Ws[cur][kk][nb];
                acc[0][0] += av.x * bv.x; acc[0][1] += av.x * bv.y;
                acc[1][0] += av.y * bv.x; acc[1][1] += av.y * bv.y;
            }
            if (c < 15) {
#pragma unroll
                for (int it = 0; it < 8; it++) {
                    int lin = tid + (it << 8);
                    int kk = lin & 63, b = lin >> 6;
                    Hs[nxt][kk][b] = hreg[it];
                }
#pragma unroll
                for (int it = 0; it < 8; it++) {
                    int lin = tid + (it << 8);
                    int kk = lin & 63, n = lin >> 6;
                    Ws[nxt][kk][n] = wreg[it];
                }
            }
            __syncthreads();
        }
    }

#pragma unroll
    for (int i = 0; i < 2; i++) {
        int b = mb + i;
#pragma unroll
        for (int j = 0; j < 2; j++) {
            int n = nb + j;
            int col = ((n >> 3) << 10) + j0 + (n & 7);
            Gs[b][n] = acc[i][j] + g_Xg[((size_t)b * LL + t) * G4 + col];
        }
    }
    __syncthreads();

    {
        int b = tid >> 3;
        int jj = tid & 7;
        float gi = Gs[b][jj];
        float gf = Gs[b][8 + jj];
        float gg = Gs[b][16 + jj];
        float go = Gs[b][24 + jj];
        float cp = (t > 0) ? g_cs[((size_t)b * LL + (t - 1)) * HH + j0 + jj] : 0.0f;
        float c = sigf(gf) * cp + sigf(gi) * tanhf(gg);
        float h = sigf(go) * tanhf(c);
        g_hs[((size_t)b * LL + t) * HH + j0 + jj] = h;
        g_cs[((size_t)b * LL + t) * HH + j0 + jj] = c;
    }
}

// =====================================================================
// K4: device-side greedy tree build (1 thread per batch)
// =====================================================================
__global__ void build_tree(const int* __restrict__ words, const int* __restrict__ length) {
    int tid = threadIdx.x;
    if (tid < LL) g_lvl_cnt[tid] = 0;
    __syncthreads();
    if (tid >= BB) return;
    int b = tid;
    const int* w = words + b * LL;
    int nlen = length[b];
    int df[LL];
    for (int i = 0; i < nlen; i++) df[i] = w[i] % 1000;

    int st_start[132], st_end[132], st_pos[132], st_stage[132], st_left[132], st_llvl[132];
    int sp = 0;
    st_start[0] = 0; st_end[0] = nlen; st_stage[0] = 0;
    int retE = -1, retL = 0;
    int localCount = 0;

    while (sp >= 0) {
        int stage = st_stage[sp];
        if (stage == 0) {
            int s = st_start[sp], e = st_end[sp], n = e - s;
            if (n == 0) { retE = -1; retL = 0; sp--; }
            else if (n == 1) { retE = 100000 + b * LL + s; retL = 0; sp--; }
            else {
                int best = s;
                for (int i = s + 1; i < e; i++)
                    if (df[i] < df[best]) best = i;
                st_pos[sp] = best;
                st_stage[sp] = 1;
                sp++;
                st_start[sp] = s; st_end[sp] = best; st_stage[sp] = 0;
            }
        } else if (stage == 1) {
            st_left[sp] = retE; st_llvl[sp] = retL; st_stage[sp] = 2;
            int p = st_pos[sp];
            int e = st_end[sp];
            sp++;
            st_start[sp] = p + 1; st_end[sp] = e; st_stage[sp] = 0;
        } else {
            int id = b * 127 + (localCount++);
            g_nl[id] = st_left[sp];
            g_nr[id] = retE;
            g_nx[id] = b * LL + st_pos[sp];
            int lvl = 1 + (st_llvl[sp] > retL ? st_llvl[sp] : retL);
            int pos = atomicAdd(&g_lvl_cnt[lvl], 1);
            g_lvl_list[lvl * LVMAX + pos] = id;
            retE = id; retL = lvl;
            sp--;
        }
    }
    g_root[b] = retE;
}

// =====================================================================
// K6: compose GEMM — wmma tf32, split-K 4 (short chains) + register-
// prefetch DOUBLE BUFFERING (latency hiding).
//   gp[ks][m][n] = A[m][kb:kb+768] . W_comp[n][kb:kb+768]
// Tile 64x128: 8 warps 2(m)x4(n), warp = 2x2 wmma m16n16k8.
// K slice in 48 chunks of 16; next chunk prefetched to registers while
// current computes; ping-pong smem pad 24 (36.9 KB); one barrier/chunk.
// 16-chunk never crosses a 1024 h-segment boundary (16 | 1024).
// =====================================================================
__global__ __launch_bounds__(256) void compose_gemm(int lvl, const float* __restrict__ Wc) {
    int cnt = g_lvl_cnt[lvl];
    if (cnt == 0) return;
    __shared__ __align__(32) float As[2][64][24];
    __shared__ __align__(32) float Bs[2][128][24];
    __shared__ const float* rph[64][3];
    const int tid = threadIdx.x;
    const int wid = tid >> 5;
    const int n0 = blockIdx.x << 7;
    const int ks = blockIdx.z;
    const int kb = ks * KSLICE;
    const int wm = (wid & 1) << 5;
    const int wn = (wid >> 1) << 5;
    const int sr = tid >> 4;          // 0..15
    const int sk = tid & 15;          // k within 16-chunk
    float* gp = g_gp + (size_t)ks * LVMAX * G6;

    for (int mt = blockIdx.y; mt * 64 < cnt; mt += gridDim.y) {
        int m0 = mt << 6;
        if (tid < 192) {
            int r = tid / 3, s = tid % 3;
            int m = m0 + r;
            const float* p = nullptr;
            if (m < cnt) {
                int id = g_lvl_list[lvl * LVMAX + m];
                int enc = (s == 0) ? g_nl[id] : (s == 1 ? (100000 + g_nx[id]) : g_nr[id]);
                if (enc >= 100000) p = g_hs + (size_t)(enc - 100000) * HH;
                else if (enc >= 0) p = g_nh + (size_t)enc * HH;
            }
            rph[r][s] = p;
        }
        __syncthreads();

        wmma::fragment<wmma::accumulator, 16, 16, 8, float> cf[2][2];
#pragma unroll
        for (int i = 0; i < 2; i++)
#pragma unroll
            for (int j = 0; j < 2; j++) wmma::fill_fragment(cf[i][j], 0.0f);

        // prologue: chunk 0 of this slice -> buf 0
        {
            int seg = kb >> 10;
            int koff = (kb & 1023) + sk;
#pragma unroll
            for (int it = 0; it < 4; it++) {
                int r = sr + (it << 4);
                const float* p = rph[r][seg];
                As[0][r][sk] = wmma::__float_to_tf32(p ? p[koff] : 0.0f);
            }
#pragma unroll
            for (int it = 0; it < 8; it++) {
                int n = sr + (it << 4);
                Bs[0][n][sk] = wmma::__float_to_tf32(Wc[(size_t)(n0 + n) * K3 + kb + sk]);
            }
        }
        __syncthreads();

        for (int c = 0; c < NCHUNK; c++) {
            const int cur = c & 1;
            const int nxt = cur ^ 1;
            float aReg[4], bReg[8];
            if (c < NCHUNK - 1) {
                int k0 = kb + ((c + 1) << 4);
                int seg = k0 >> 10;
                int koff = (k0 & 1023) + sk;
#pragma unroll
                for (int it = 0; it < 4; it++) {
                    int r = sr + (it << 4);
                    const float* p = rph[r][seg];
                    aReg[it] = p ? p[koff] : 0.0f;
                }
#pragma unroll
                for (int it = 0; it < 8; it++) {
                    int n = sr + (it << 4);
                    bReg[it] = Wc[(size_t)(n0 + n) * K3 + k0 + sk];
                }
            }
#pragma unroll
            for (int kq = 0; kq < 16; kq += 8) {
                wmma::fragment<wmma::matrix_a, 16, 16, 8, wmma::precision::tf32, wmma::row_major> af[2];
                wmma::fragment<wmma::matrix_b, 16, 16, 8, wmma::precision::tf32, wmma::col_major> bf[2];
                wmma::load_matrix_sync(af[0], &As[cur][wm][kq], 24);
                wmma::load_matrix_sync(af[1], &As[cur][wm + 16][kq], 24);
                wmma::load_matrix_sync(bf[0], &Bs[cur][wn][kq], 24);
                wmma::load_matrix_sync(bf[1], &Bs[cur][wn + 16][kq], 24);
#pragma unroll
                for (int i = 0; i < 2; i++)
#pragma unroll
                    for (int j = 0; j < 2; j++)
                        wmma::mma_sync(cf[i][j], af[i], bf[j], cf[i][j]);
            }
            if (c < NCHUNK - 1) {
#pragma unroll
                for (int it = 0; it < 4; it++)
                    As[nxt][sr + (it << 4)][sk] = wmma::__float_to_tf32(aReg[it]);
#pragma unroll
                for (int it = 0; it < 8; it++)
                    Bs[nxt][sr + (it << 4)][sk] = wmma::__float_to_tf32(bReg[it]);
            }
            __syncthreads();
        }

#pragma unroll
        for (int i = 0; i < 2; i++)
#pragma unroll
            for (int j = 0; j < 2; j++)
                wmma::store_matrix_sync(
                    &gp[(size_t)(m0 + wm + i * 16) * G6 + n0 + wn + j * 16],
                    cf[i][j], G6, wmma::mem_row_major);
        __syncthreads();
    }
}

// =====================================================================
// K7: compose pointwise for level lvl; sums 4 K-partials
// =====================================================================
__device__ __forceinline__ float fetch_c(int enc, int j) {
    if (enc < 0) return 0.0f;
    if (enc >= 100000) return g_cs[(size_t)(enc - 100000) * HH + j];
    return g_nc[(size_t)enc * HH + j];
}

__global__ __launch_bounds__(256) void compose_point(int lvl, const float* __restrict__ bc) {
    int cnt = g_lvl_cnt[lvl];
    int total = cnt * HH;
    int stride = gridDim.x * blockDim.x;
    for (int idx = blockIdx.x * blockDim.x + threadIdx.x; idx < total; idx += stride) {
        int m = idx >> 10;
        int j = idx & 1023;
        int id = g_lvl_list[lvl * LVMAX + m];
        float a[6];
#pragma unroll
        for (int s = 0; s < 6; s++) {
            size_t off = (size_t)m * G6 + (s << 10) + j;
            float v = bc[(s << 10) + j];
#pragma unroll
            for (int ks = 0; ks < KSPLIT; ks++)
                v += g_gp[(size_t)ks * LVMAX * G6 + off];
            a[s] = v;
        }
        int le = g_nl[id], re = g_nr[id], xs = g_nx[id];
        float cl = fetch_c(le, j);
        float cr = fetch_c(re, j);
        float cx = g_cs[(size_t)xs * HH + j];
        float c = sigf(a[0]) * tanhf(a[4]) + sigf(a[1]) * cl + sigf(a[2]) * cx + sigf(a[3]) * cr;
        float h = sigf(a[5]) * tanhf(c);
        g_nh[(size_t)id * HH + j] = h;
        g_nc[(size_t)id * HH + j] = c;
    }
}

// =====================================================================
// K8: gather roots -> output  [h (B,H) ; c (B,H)]
// =====================================================================
__global__ __launch_bounds__(256) void write_out(float* __restrict__ out) {
    int stride = gridDim.x * blockDim.x;
    for (int idx = blockIdx.x * blockDim.x + threadIdx.x; idx < BB * HH; idx += stride) {
        int b = idx >> 10;
        int j = idx & 1023;
        int r = g_root[b];
        out[idx] = g_nh[(size_t)r * HH + j];
        out[BB * HH + idx] = g_nc[(size_t)r * HH + j];
    }
}

// =====================================================================
extern "C" void kernel_launch(void* const* d_in, const int* in_sizes, int n_in,
                              void* d_out, int out_size) {
    const float* X    = (const float*)d_in[0];
    const float* Wih  = (const float*)d_in[1];
    const float* Whh  = (const float*)d_in[2];
    const float* bih  = (const float*)d_in[3];
    const float* bhh  = (const float*)d_in[4];
    const float* Wc   = (const float*)d_in[5];
    const float* bc   = (const float*)d_in[6];
    const int* words  = (const int*)d_in[7];
    const int* length = (const int*)d_in[8];
    float* out = (float*)d_out;

    xg_gemm<<<dim3(64, 64), 256>>>(X, Wih, bih, bhh);
    build_tree<<<1, 128>>>(words, length);

    for (int t = 0; t < LL; t++)
        lstm_step<<<128, 256>>>(t, Whh);

    for (int lvl = 1; lvl < LL; lvl++) {
        compose_gemm<<<dim3(48, 8, KSPLIT), 256>>>(lvl, Wc);
        compose_point<<<64, 256>>>(lvl, bc);
    }

    write_out<<<32, 256>>>(out);
}